// round 3
// baseline (speedup 1.0000x reference)
#include <cuda_runtime.h>

#define B_ROWS 16384
#define NN     128
#define NS     1024
#define GRID_MAIN 444            // 3 blocks/SM * 148 SMs, single wave
#define BLOCK_MAIN 256
#define LANES (GRID_MAIN * 2)

// ---------------- scratch (device globals; statically zero-initialized) ----------------
// Invariant: zero at entry of every kernel_launch; finalizing block resets.
__device__ float g_nU[NN];      // sum y*softplus(-x)  (narrative, pw-weighted part)
__device__ float g_nC[NN];      // sum y
__device__ float g_sP[NS];      // sum g*s*softplus(x) (sub)
__device__ float g_sR[NS];      // sum g*s*x
__device__ float g_sC[NS];      // sum s (ungated)
__device__ float g_scl[8];      // 0=Qt (sum g*spx_sub), 1=Wn (sum (1-g)*spx_narr), 2=hier, 3=nf, 4=sf
__device__ unsigned int g_ctr;

__device__ __forceinline__ float softplus_f(float x) {
    // softplus(x) = max(x,0) + log1p(exp(-|x|)); EX2 + LG2
    float e = exp2f(-1.4426950408889634f * fabsf(x));
    float L = 0.6931471805599453f * __log2f(1.0f + e);
    return fmaxf(x, 0.0f) + L;
}

__global__ __launch_bounds__(BLOCK_MAIN, 3)
void fused_kernel(const float* __restrict__ nlg, const float* __restrict__ slg,
                  const int* __restrict__ nlb,  const int* __restrict__ slb,
                  float* __restrict__ out)
{
    const int tid  = threadIdx.x;
    const int n    = tid & 127;                     // narrative class owned
    const int lane = blockIdx.x * 2 + (tid >> 7);   // row-processor id

    float Un = 0.f;
    float P[8], R[8];
#pragma unroll
    for (int k = 0; k < 8; k++) { P[k] = 0.f; R[k] = 0.f; }
    float Qt = 0.f, Wn = 0.f, hier = 0.f, nf = 0.f, sf = 0.f;
    int cn = 0, ca = 0, cb = 0;   // packed byte-lane counts (<=19 per byte, safe)

    const float4* sp  = (const float4*)slg + (size_t)lane * (NS / 4) + n * 2;
    const int4*   slp = (const int4*)slb   + (size_t)lane * (NS / 4) + n * 2;
    const float*  np  = nlg + (size_t)lane * NN + n;
    const int*    nbp = nlb + (size_t)lane * NN + n;
    const size_t  sstep = (size_t)LANES * (NS / 4);
    const size_t  nstep = (size_t)LANES * NN;

    const int iters = ((B_ROWS - 1 - lane) / LANES) + 1;

    // ---- prologue: prefetch iteration 0 ----
    float4 v0 = sp[0], v1 = sp[1];
    int4   l0 = slp[0], l1 = slp[1];
    float  xn = *np;
    int    gi = *nbp;

    for (int i = 0; i < iters; i++) {
        sp += sstep; slp += sstep; np += nstep; nbp += nstep;

        // ---- prefetch iteration i+1 (predicated; hides DRAM latency behind compute) ----
        float4 nv0, nv1; int4 nl0, nl1; float nxn; int ngi;
        if (i + 1 < iters) {
            nv0 = sp[0]; nv1 = sp[1];
            nl0 = slp[0]; nl1 = slp[1];
            nxn = *np;   ngi = *nbp;
        }

        float g = (float)gi;

        // ---- narrative element ----
        float spn  = softplus_f(xn);
        float spmn = spn - xn;                          // softplus(-x)
        float wn   = exp2f(-2.8853900817779268f * spn); // (1-sigmoid)^2
        nf = fmaf(g * wn, -spmn, nf);                   // g*(1-p)^2 * log sigmoid
        Un = fmaf(g, spmn, Un);
        Wn = fmaf(1.0f - g, spn, Wn);
        cn += gi;
        float pn = exp2f(-1.4426950408889634f * spmn);  // sigmoid(xn)

        // ---- 8 subnarrative elements of this group ----
        float xs[8] = { v0.x, v0.y, v0.z, v0.w, v1.x, v1.y, v1.z, v1.w };
        int   li[8] = { l0.x, l0.y, l0.z, l0.w, l1.x, l1.y, l1.z, l1.w };
        float mx = xs[0];
#pragma unroll
        for (int k = 0; k < 8; k++) {
            float x   = xs[k];
            float s   = (float)li[k];
            float spx = softplus_f(x);
            float w   = exp2f(-2.8853900817779268f * spx);
            sf = fmaf(s * w, x - spx, sf);              // s*(1-p)^2*log sigmoid
            float gs = g * s;
            P[k] = fmaf(gs, spx, P[k]);
            R[k] = fmaf(gs, x,   R[k]);
            Qt   = fmaf(g,  spx, Qt);
            mx   = fmaxf(mx, x);
        }
        ca += li[0] + (li[1] << 8) + (li[2] << 16) + (li[3] << 24);
        cb += li[4] + (li[5] << 8) + (li[6] << 16) + (li[7] << 24);

        // ---- hierarchy: max(sigmoid)=sigmoid(max) ----
        float em = exp2f(-1.4426950408889634f * mx);
        float pm = __fdividef(1.0f, 1.0f + em);
        hier = fmaf(g, fmaxf(pm - pn, 0.0f), hier);

        // rotate double-buffer
        v0 = nv0; v1 = nv1; l0 = nl0; l1 = nl1; xn = nxn; gi = ngi;
    }

    // ---------------- pair the two 128-lane halves in shared ----------------
    __shared__ float sh[128][25];    // odd stride -> conflict-free
    if (tid >= 128) {
        float* d = sh[tid - 128];
        d[0] = Un;
#pragma unroll
        for (int k = 0; k < 8; k++) { d[1 + k] = P[k]; d[9 + k] = R[k]; }
        d[17] = Qt; d[18] = Wn; d[19] = hier; d[20] = nf; d[21] = sf;
        d[22] = __int_as_float(cn); d[23] = __int_as_float(ca); d[24] = __int_as_float(cb);
    }
    __syncthreads();

    if (tid < 128) {
        float* d = sh[tid];
        Un += d[0];
#pragma unroll
        for (int k = 0; k < 8; k++) { P[k] += d[1 + k]; R[k] += d[9 + k]; }
        Qt += d[17]; Wn += d[18]; hier += d[19]; nf += d[20]; sf += d[21];
        cn += __float_as_int(d[22]);
        ca += __float_as_int(d[23]);
        cb += __float_as_int(d[24]);

        atomicAdd(&g_nU[n], Un);
        atomicAdd(&g_nC[n], (float)cn);
#pragma unroll
        for (int k = 0; k < 8; k++) {
            atomicAdd(&g_sP[n * 8 + k], P[k]);
            atomicAdd(&g_sR[n * 8 + k], R[k]);
        }
#pragma unroll
        for (int k = 0; k < 4; k++) {
            atomicAdd(&g_sC[n * 8 + k],     (float)((ca >> (8 * k)) & 255));
            atomicAdd(&g_sC[n * 8 + 4 + k], (float)((cb >> (8 * k)) & 255));
        }
    }

    // scalar block-reduce over lower 128 threads (4 full warps)
    __shared__ float sw[5][4];
    if (tid < 128) {
#pragma unroll
        for (int o = 16; o; o >>= 1) {
            Qt   += __shfl_down_sync(0xffffffffu, Qt,   o);
            Wn   += __shfl_down_sync(0xffffffffu, Wn,   o);
            hier += __shfl_down_sync(0xffffffffu, hier, o);
            nf   += __shfl_down_sync(0xffffffffu, nf,   o);
            sf   += __shfl_down_sync(0xffffffffu, sf,   o);
        }
        if ((tid & 31) == 0) {
            int w = tid >> 5;
            sw[0][w] = Qt; sw[1][w] = Wn; sw[2][w] = hier; sw[3][w] = nf; sw[4][w] = sf;
        }
    }
    __syncthreads();
    if (tid == 0) {
        atomicAdd(&g_scl[0], sw[0][0] + sw[0][1] + sw[0][2] + sw[0][3]);
        atomicAdd(&g_scl[1], sw[1][0] + sw[1][1] + sw[1][2] + sw[1][3]);
        atomicAdd(&g_scl[2], sw[2][0] + sw[2][1] + sw[2][2] + sw[2][3]);
        atomicAdd(&g_scl[3], sw[3][0] + sw[3][1] + sw[3][2] + sw[3][3]);
        atomicAdd(&g_scl[4], sw[4][0] + sw[4][1] + sw[4][2] + sw[4][3]);
    }

    // ---------------- last block finalizes and resets scratch ----------------
    __threadfence();
    __shared__ unsigned int s_last;
    if (tid == 0) s_last = (atomicAdd(&g_ctr, 1u) == (unsigned)(gridDim.x - 1)) ? 1u : 0u;
    __syncthreads();
    if (!s_last) return;
    __threadfence();

    double subAcc = 0.0, narrAcc = 0.0, valid = 0.0;
    for (int c = tid; c < NS; c += BLOCK_MAIN) {
        float Pv = g_sP[c], Rv = g_sR[c], Cv = g_sC[c];
        float pw = fminf(fmaxf((16384.0f - Cv) / (Cv + 1e-6f), 1.0f), 50.0f);
        subAcc += (double)pw * (double)(Pv - Rv) - (double)Pv;
    }
    for (int c = tid; c < NN; c += BLOCK_MAIN) {
        float Uv = g_nU[c], Cv = g_nC[c];
        float pw = fminf(fmaxf((16384.0f - Cv) / (Cv + 1e-6f), 1.0f), 50.0f);
        narrAcc += (double)pw * (double)Uv;
        valid   += (double)Cv;
    }
#pragma unroll
    for (int o = 16; o; o >>= 1) {
        subAcc  += __shfl_down_sync(0xffffffffu, subAcc,  o);
        narrAcc += __shfl_down_sync(0xffffffffu, narrAcc, o);
        valid   += __shfl_down_sync(0xffffffffu, valid,   o);
    }
    __shared__ double rd[24];
    if ((tid & 31) == 0) {
        int w = tid >> 5;   // 8 warps
        rd[w] = subAcc; rd[8 + w] = narrAcc; rd[16 + w] = valid;
    }
    __syncthreads();
    if (tid == 0) {
        double ss = 0.0, ns = 0.0, vv = 0.0;
        for (int i = 0; i < 8; i++) { ss += rd[i]; ns += rd[8 + i]; vv += rd[16 + i]; }
        double Qts = g_scl[0], Wns = g_scl[1], hs = g_scl[2], nfs = g_scl[3], sfs = g_scl[4];

        double narrative_loss = (ns + Wns) / (16384.0 * 128.0);
        double sub_loss = (vv > 0.0) ? ((ss + Qts) / 8.0) / fmax(vv, 1.0) : 0.0;
        double total = (narrative_loss - 0.1 * nfs / (16384.0 * 128.0))
                     + (sub_loss       - 0.1 * sfs / (16384.0 * 1024.0))
                     + 0.5 * hs / 16384.0;
        out[0] = (float)total;
    }
    __syncthreads();

    // reset scratch for the next graph replay
    for (int i = tid; i < NS; i += BLOCK_MAIN) { g_sP[i] = 0.f; g_sR[i] = 0.f; g_sC[i] = 0.f; }
    for (int i = tid; i < NN; i += BLOCK_MAIN) { g_nU[i] = 0.f; g_nC[i] = 0.f; }
    if (tid < 8) g_scl[tid] = 0.f;
    if (tid == 0) g_ctr = 0u;
}

extern "C" void kernel_launch(void* const* d_in, const int* in_sizes, int n_in,
                              void* d_out, int out_size)
{
    const float* nlg = (const float*)d_in[0];   // narrative_logits [B,128]
    const float* slg = (const float*)d_in[1];   // subnarrative_logits [B,1024]
    const int*   nlb = (const int*)d_in[2];     // narrative_labels [B,128]
    const int*   slb = (const int*)d_in[3];     // subnarrative_labels [B,1024]
    (void)in_sizes; (void)n_in; (void)out_size;

    fused_kernel<<<GRID_MAIN, BLOCK_MAIN>>>(nlg, slg, nlb, slb, (float*)d_out);
}

// round 6
// speedup vs baseline: 1.6738x; 1.6738x over previous
#include <cuda_runtime.h>

#define B_ROWS 16384
#define NN     128
#define NS     1024
#define GRID_MAIN 296            // 2 blocks/SM * 148 SMs
#define BLOCK_MAIN 256
#define LANES (GRID_MAIN * 2)
#define NSHARD 4

// ---------------- scratch (device globals; statically zero-initialized) ----------------
// Invariant: zero at entry of every kernel_launch; finalizing block resets.
__device__ float g_sA[NSHARD][NS];   // sum g*s*softplus(-x)  (sub, pw-weighted part)
__device__ float g_sC[NSHARD][NS];   // sum s (ungated column count)
__device__ float g_nU[NSHARD][NN];   // sum y*softplus(-x)    (narrative)
__device__ float g_nC[NSHARD][NN];   // sum y
__device__ float g_scl[8];           // 0=Qt(sum g*spx_sub) 1=Ptot(sum g*s*spx_sub) 2=Wn(sum (1-g)*spx_narr) 3=hier 4=nf 5=sf
__device__ unsigned int g_ctr;

__device__ __forceinline__ float softplus_f(float x) {
    // softplus(x) = max(x,0) + log1p(exp(-|x|)); EX2 + LG2
    float e = exp2f(-1.4426950408889634f * fabsf(x));
    float L = __log2f(1.0f + e);
    return fmaxf(x, 0.0f) + 0.6931471805599453f * L;
}

__global__ __launch_bounds__(BLOCK_MAIN, 2)
void fused_kernel(const float* __restrict__ nlg, const float* __restrict__ slg,
                  const int* __restrict__ nlb,  const int* __restrict__ slb,
                  float* __restrict__ out)
{
    const int tid  = threadIdx.x;
    const int n    = tid & 127;                     // narrative class owned
    const int lane = blockIdx.x * 2 + (tid >> 7);   // row-processor id

    float A[8];
#pragma unroll
    for (int k = 0; k < 8; k++) A[k] = 0.f;
    float Un = 0.f, Qt = 0.f, Pt = 0.f, Wn = 0.f, hier = 0.f, nf = 0.f, sf = 0.f;
    int cn = 0, ca = 0, cb = 0;   // packed byte-lane counts (<=28 per byte, safe)

    const float4* sp  = (const float4*)slg + (size_t)lane * (NS / 4) + n * 2;
    const int4*   slp = (const int4*)slb   + (size_t)lane * (NS / 4) + n * 2;
    const float*  np  = nlg + (size_t)lane * NN + n;
    const int*    nbp = nlb + (size_t)lane * NN + n;
    const size_t  sstep = (size_t)LANES * (NS / 4);
    const size_t  nstep = (size_t)LANES * NN;

    for (int r = lane; r < B_ROWS; r += LANES) {
        float4 v0 = __ldcs(sp);
        float4 v1 = __ldcs(sp + 1);
        int4   l0 = __ldcs(slp);
        int4   l1 = __ldcs(slp + 1);
        float  xn = __ldcs(np);
        int    gi = __ldcs(nbp);
        sp += sstep; slp += sstep; np += nstep; nbp += nstep;

        float g = (float)gi;

        // ---- narrative element ----
        float spn  = softplus_f(xn);
        float spmn = spn - xn;                          // softplus(-x) = -log sigmoid(x)
        float wn   = exp2f(-2.8853900817779268f * spn); // (1-sigmoid)^2
        nf = fmaf(g * wn, -spmn, nf);
        Un = fmaf(g, spmn, Un);
        Wn = fmaf(1.0f - g, spn, Wn);
        cn += gi;
        float pn = exp2f(-1.4426950408889634f * spmn);  // sigmoid(xn)

        // ---- 8 subnarrative elements of this group ----
        float xs[8] = { v0.x, v0.y, v0.z, v0.w, v1.x, v1.y, v1.z, v1.w };
        int   li[8] = { l0.x, l0.y, l0.z, l0.w, l1.x, l1.y, l1.z, l1.w };
        float mx = xs[0];
#pragma unroll
        for (int k = 0; k < 8; k++) {
            float x   = xs[k];
            float s   = __int_as_float(li[k] * 0x3f800000);  // 0/1 -> 0.0f/1.0f, 1 IMAD
            float spx = softplus_f(x);
            float spm = spx - x;
            float w   = exp2f(-2.8853900817779268f * spx);   // (1-p)^2
            sf  = fmaf(s * w, -spm, sf);                     // s*(1-p)^2*log sigmoid
            float gs = g * s;
            A[k] = fmaf(gs, spm, A[k]);
            Pt   = fmaf(gs, spx, Pt);
            Qt   = fmaf(g,  spx, Qt);
            mx   = fmaxf(mx, x);
        }
        ca += li[0] + (li[1] << 8) + (li[2] << 16) + (li[3] << 24);
        cb += li[4] + (li[5] << 8) + (li[6] << 16) + (li[7] << 24);

        // ---- hierarchy: max(sigmoid)=sigmoid(max) ----
        float em = exp2f(-1.4426950408889634f * mx);
        float pm = __fdividef(1.0f, 1.0f + em);
        hier = fmaf(g, fmaxf(pm - pn, 0.0f), hier);
    }

    // ---------------- pair the two 128-lane halves in shared ----------------
    __shared__ float sh[128][19];    // odd stride -> conflict-free
    if (tid >= 128) {
        float* d = sh[tid - 128];
#pragma unroll
        for (int k = 0; k < 8; k++) d[k] = A[k];
        d[8] = Un; d[9] = Qt; d[10] = Pt; d[11] = Wn; d[12] = hier; d[13] = nf; d[14] = sf;
        d[15] = __int_as_float(cn); d[16] = __int_as_float(ca); d[17] = __int_as_float(cb);
    }
    __syncthreads();

    const int shard = blockIdx.x & (NSHARD - 1);
    if (tid < 128) {
        float* d = sh[tid];
#pragma unroll
        for (int k = 0; k < 8; k++) A[k] += d[k];
        Un += d[8]; Qt += d[9]; Pt += d[10]; Wn += d[11]; hier += d[12]; nf += d[13]; sf += d[14];
        cn += __float_as_int(d[15]);
        ca += __float_as_int(d[16]);
        cb += __float_as_int(d[17]);

        atomicAdd(&g_nU[shard][n], Un);
        atomicAdd(&g_nC[shard][n], (float)cn);
#pragma unroll
        for (int k = 0; k < 8; k++)
            atomicAdd(&g_sA[shard][n * 8 + k], A[k]);
#pragma unroll
        for (int k = 0; k < 4; k++) {
            atomicAdd(&g_sC[shard][n * 8 + k],     (float)((ca >> (8 * k)) & 255));
            atomicAdd(&g_sC[shard][n * 8 + 4 + k], (float)((cb >> (8 * k)) & 255));
        }
    }

    // scalar block-reduce over lower 128 threads (4 full warps)
    __shared__ float sw[6][4];
    if (tid < 128) {
#pragma unroll
        for (int o = 16; o; o >>= 1) {
            Qt   += __shfl_down_sync(0xffffffffu, Qt,   o);
            Pt   += __shfl_down_sync(0xffffffffu, Pt,   o);
            Wn   += __shfl_down_sync(0xffffffffu, Wn,   o);
            hier += __shfl_down_sync(0xffffffffu, hier, o);
            nf   += __shfl_down_sync(0xffffffffu, nf,   o);
            sf   += __shfl_down_sync(0xffffffffu, sf,   o);
        }
        if ((tid & 31) == 0) {
            int w = tid >> 5;
            sw[0][w] = Qt; sw[1][w] = Pt; sw[2][w] = Wn;
            sw[3][w] = hier; sw[4][w] = nf; sw[5][w] = sf;
        }
    }
    __syncthreads();
    if (tid < 6) {
        float v = sw[tid][0] + sw[tid][1] + sw[tid][2] + sw[tid][3];
        atomicAdd(&g_scl[tid], v);
    }

    // ---------------- last block finalizes and resets scratch ----------------
    __threadfence();
    __shared__ unsigned int s_last;
    if (tid == 0) s_last = (atomicAdd(&g_ctr, 1u) == (unsigned)(gridDim.x - 1)) ? 1u : 0u;
    __syncthreads();
    if (!s_last) return;
    __threadfence();

    double subAcc = 0.0, narrAcc = 0.0, valid = 0.0;
    for (int c = tid; c < NS; c += BLOCK_MAIN) {
        float Av = g_sA[0][c] + g_sA[1][c] + g_sA[2][c] + g_sA[3][c];
        float Cv = g_sC[0][c] + g_sC[1][c] + g_sC[2][c] + g_sC[3][c];
        float pw = fminf(fmaxf((16384.0f - Cv) / (Cv + 1e-6f), 1.0f), 50.0f);
        subAcc += (double)pw * (double)Av;
    }
    for (int c = tid; c < NN; c += BLOCK_MAIN) {
        float Uv = g_nU[0][c] + g_nU[1][c] + g_nU[2][c] + g_nU[3][c];
        float Cv = g_nC[0][c] + g_nC[1][c] + g_nC[2][c] + g_nC[3][c];
        float pw = fminf(fmaxf((16384.0f - Cv) / (Cv + 1e-6f), 1.0f), 50.0f);
        narrAcc += (double)pw * (double)Uv;
        valid   += (double)Cv;
    }
#pragma unroll
    for (int o = 16; o; o >>= 1) {
        subAcc  += __shfl_down_sync(0xffffffffu, subAcc,  o);
        narrAcc += __shfl_down_sync(0xffffffffu, narrAcc, o);
        valid   += __shfl_down_sync(0xffffffffu, valid,   o);
    }
    __shared__ double rd[24];
    if ((tid & 31) == 0) {
        int w = tid >> 5;   // 8 warps
        rd[w] = subAcc; rd[8 + w] = narrAcc; rd[16 + w] = valid;
    }
    __syncthreads();
    if (tid == 0) {
        double ss = 0.0, ns = 0.0, vv = 0.0;
        for (int i = 0; i < 8; i++) { ss += rd[i]; ns += rd[8 + i]; vv += rd[16 + i]; }
        double Qts = g_scl[0], Pts = g_scl[1], Wns = g_scl[2];
        double hs = g_scl[3], nfs = g_scl[4], sfs = g_scl[5];

        // sub BCE total over gated elements: sum_c pw_c*A_c + (Qt - Ptot)
        double sub_total = ss + Qts - Pts;
        double narrative_loss = (ns + Wns) / (16384.0 * 128.0);
        double sub_loss = (vv > 0.0) ? (sub_total / 8.0) / fmax(vv, 1.0) : 0.0;
        double total = (narrative_loss - 0.1 * nfs / (16384.0 * 128.0))
                     + (sub_loss       - 0.1 * sfs / (16384.0 * 1024.0))
                     + 0.5 * hs / 16384.0;
        out[0] = (float)total;
    }
    __syncthreads();

    // reset scratch for the next graph replay
    for (int i = tid; i < NSHARD * NS; i += BLOCK_MAIN) {
        ((float*)g_sA)[i] = 0.f; ((float*)g_sC)[i] = 0.f;
    }
    for (int i = tid; i < NSHARD * NN; i += BLOCK_MAIN) {
        ((float*)g_nU)[i] = 0.f; ((float*)g_nC)[i] = 0.f;
    }
    if (tid < 8) g_scl[tid] = 0.f;
    if (tid == 0) g_ctr = 0u;
}

extern "C" void kernel_launch(void* const* d_in, const int* in_sizes, int n_in,
                              void* d_out, int out_size)
{
    const float* nlg = (const float*)d_in[0];   // narrative_logits [B,128]
    const float* slg = (const float*)d_in[1];   // subnarrative_logits [B,1024]
    const int*   nlb = (const int*)d_in[2];     // narrative_labels [B,128]
    const int*   slb = (const int*)d_in[3];     // subnarrative_labels [B,1024]
    (void)in_sizes; (void)n_in; (void)out_size;

    fused_kernel<<<GRID_MAIN, BLOCK_MAIN>>>(nlg, slg, nlb, slb, (float*)d_out);
}

// round 7
// speedup vs baseline: 1.7312x; 1.0343x over previous
#include <cuda_runtime.h>

#define B_ROWS 16384
#define NN     128
#define NS     1024
#define GRID_MAIN 444            // 3 blocks/SM * 148 SMs, single wave
#define BLOCK_MAIN 256
#define LANES (GRID_MAIN * 2)
#define NSHARD 4

// ---------------- scratch (device globals; statically zero-initialized) ----------------
// Invariant: zero at entry of every kernel_launch; finalizing block resets.
__device__ float g_sA[NSHARD][NS];   // sum g*s*softplus(-x)  (sub, pw-weighted part)
__device__ float g_sC[NSHARD][NS];   // sum s (ungated column count)
__device__ float g_nU[NSHARD][NN];   // sum y*softplus(-x)    (narrative)
__device__ float g_nC[NSHARD][NN];   // sum y
__device__ float g_scl[8];           // 0=Qs(sum g*(1-s)*spx_sub) 1=Wn(sum (1-g)*spx_narr) 2=hier 3=nf 4=sf
__device__ unsigned int g_ctr;

__device__ __forceinline__ float softplus_f(float x) {
    // softplus(x) = max(x,0) + log1p(exp(-|x|)); EX2 + LG2
    float e = exp2f(-1.4426950408889634f * fabsf(x));
    float L = __log2f(1.0f + e);
    return fmaxf(x, 0.0f) + 0.6931471805599453f * L;
}

__global__ __launch_bounds__(BLOCK_MAIN, 3)
void fused_kernel(const float* __restrict__ nlg, const float* __restrict__ slg,
                  const int* __restrict__ nlb,  const int* __restrict__ slb,
                  float* __restrict__ out)
{
    const int tid  = threadIdx.x;
    const int n    = tid & 127;                     // narrative class owned
    const int lane = blockIdx.x * 2 + (tid >> 7);   // row-processor id

    float A[8];
#pragma unroll
    for (int k = 0; k < 8; k++) A[k] = 0.f;
    float Un = 0.f, Qs = 0.f, Wn = 0.f, hier = 0.f, nf = 0.f, sf = 0.f;
    int cn = 0, ca = 0, cb = 0;   // packed byte-lane counts (<=19 per byte, safe)

    const float4* sp  = (const float4*)slg + (size_t)lane * (NS / 4) + n * 2;
    const int4*   slp = (const int4*)slb   + (size_t)lane * (NS / 4) + n * 2;
    const float*  np  = nlg + (size_t)lane * NN + n;
    const int*    nbp = nlb + (size_t)lane * NN + n;
    const size_t  sstep = (size_t)LANES * (NS / 4);
    const size_t  nstep = (size_t)LANES * NN;

    for (int r = lane; r < B_ROWS; r += LANES) {
        float4 v0 = __ldcs(sp);
        float4 v1 = __ldcs(sp + 1);
        int4   l0 = __ldcs(slp);
        int4   l1 = __ldcs(slp + 1);
        float  xn = __ldcs(np);
        int    gi = __ldcs(nbp);
        sp += sstep; slp += sstep; np += nstep; nbp += nstep;

        float g = (float)gi;

        // ---- narrative element: 3 MUFU (EX2, LG2, RCP) gives spx, spm, p, (1-p)^2 ----
        float e   = exp2f(-1.4426950408889634f * fabsf(xn));
        float t   = 1.0f + e;
        float q   = __fdividef(1.0f, t);                       // MUFU.RCP
        float spn = fmaxf(xn, 0.0f) + 0.6931471805599453f * __log2f(t);
        float spmn = spn - xn;                                 // softplus(-x)
        bool  posn = (xn >= 0.0f);
        float pn   = posn ? q : e * q;                         // sigmoid(xn)
        float ompn = posn ? e * q : q;                         // 1 - sigmoid(xn)
        nf = fmaf(g * ompn * ompn, -spmn, nf);
        Un = fmaf(g, spmn, Un);
        Wn = fmaf(1.0f - g, spn, Wn);
        cn += gi;

        // ---- 8 subnarrative elements of this group ----
        float xs[8] = { v0.x, v0.y, v0.z, v0.w, v1.x, v1.y, v1.z, v1.w };
        int   li[8] = { l0.x, l0.y, l0.z, l0.w, l1.x, l1.y, l1.z, l1.w };
        float mx = xs[0];
#pragma unroll
        for (int k = 0; k < 8; k++) {
            float x   = xs[k];
            float s   = __int_as_float(li[k] * 0x3f800000);  // 0/1 -> 0.0f/1.0f
            float spx = softplus_f(x);
            float spm = spx - x;
            float w   = exp2f(-2.8853900817779268f * spx);   // (1-p)^2
            sf  = fmaf(s * w, -spm, sf);                     // s*(1-p)^2*log sigmoid
            float gs = g * s;
            A[k] = fmaf(gs, spm, A[k]);
            Qs   = fmaf(g - gs, spx, Qs);                    // g*(1-s)*spx
            mx   = fmaxf(mx, x);
        }
        ca += li[0] + (li[1] << 8) + (li[2] << 16) + (li[3] << 24);
        cb += li[4] + (li[5] << 8) + (li[6] << 16) + (li[7] << 24);

        // ---- hierarchy: max(sigmoid)=sigmoid(max) ----
        float em = exp2f(-1.4426950408889634f * mx);
        float pm = __fdividef(1.0f, 1.0f + em);
        hier = fmaf(g, fmaxf(pm - pn, 0.0f), hier);
    }

    // ---------------- pair the two 128-lane halves in shared ----------------
    __shared__ float sh[128][17];    // odd stride -> conflict-free
    if (tid >= 128) {
        float* d = sh[tid - 128];
#pragma unroll
        for (int k = 0; k < 8; k++) d[k] = A[k];
        d[8] = Un; d[9] = Qs; d[10] = Wn; d[11] = hier; d[12] = nf; d[13] = sf;
        d[14] = __int_as_float(cn); d[15] = __int_as_float(ca); d[16] = __int_as_float(cb);
    }
    __syncthreads();

    const int shard = blockIdx.x & (NSHARD - 1);
    if (tid < 128) {
        float* d = sh[tid];
#pragma unroll
        for (int k = 0; k < 8; k++) A[k] += d[k];
        Un += d[8]; Qs += d[9]; Wn += d[10]; hier += d[11]; nf += d[12]; sf += d[13];
        cn += __float_as_int(d[14]);
        ca += __float_as_int(d[15]);
        cb += __float_as_int(d[16]);

        atomicAdd(&g_nU[shard][n], Un);
        atomicAdd(&g_nC[shard][n], (float)cn);
#pragma unroll
        for (int k = 0; k < 8; k++)
            atomicAdd(&g_sA[shard][n * 8 + k], A[k]);
#pragma unroll
        for (int k = 0; k < 4; k++) {
            atomicAdd(&g_sC[shard][n * 8 + k],     (float)((ca >> (8 * k)) & 255));
            atomicAdd(&g_sC[shard][n * 8 + 4 + k], (float)((cb >> (8 * k)) & 255));
        }
    }

    // scalar block-reduce over lower 128 threads (4 full warps)
    __shared__ float sw[5][4];
    if (tid < 128) {
#pragma unroll
        for (int o = 16; o; o >>= 1) {
            Qs   += __shfl_down_sync(0xffffffffu, Qs,   o);
            Wn   += __shfl_down_sync(0xffffffffu, Wn,   o);
            hier += __shfl_down_sync(0xffffffffu, hier, o);
            nf   += __shfl_down_sync(0xffffffffu, nf,   o);
            sf   += __shfl_down_sync(0xffffffffu, sf,   o);
        }
        if ((tid & 31) == 0) {
            int w = tid >> 5;
            sw[0][w] = Qs; sw[1][w] = Wn; sw[2][w] = hier; sw[3][w] = nf; sw[4][w] = sf;
        }
    }
    __syncthreads();
    if (tid < 5) {
        float v = sw[tid][0] + sw[tid][1] + sw[tid][2] + sw[tid][3];
        atomicAdd(&g_scl[tid], v);
    }

    // ---------------- last block finalizes and resets scratch ----------------
    __threadfence();
    __shared__ unsigned int s_last;
    if (tid == 0) s_last = (atomicAdd(&g_ctr, 1u) == (unsigned)(gridDim.x - 1)) ? 1u : 0u;
    __syncthreads();
    if (!s_last) return;
    __threadfence();

    double subAcc = 0.0, narrAcc = 0.0, valid = 0.0;
    for (int c = tid; c < NS; c += BLOCK_MAIN) {
        float Av = g_sA[0][c] + g_sA[1][c] + g_sA[2][c] + g_sA[3][c];
        float Cv = g_sC[0][c] + g_sC[1][c] + g_sC[2][c] + g_sC[3][c];
        float pw = fminf(fmaxf((16384.0f - Cv) / (Cv + 1e-6f), 1.0f), 50.0f);
        subAcc += (double)pw * (double)Av;
    }
    for (int c = tid; c < NN; c += BLOCK_MAIN) {
        float Uv = g_nU[0][c] + g_nU[1][c] + g_nU[2][c] + g_nU[3][c];
        float Cv = g_nC[0][c] + g_nC[1][c] + g_nC[2][c] + g_nC[3][c];
        float pw = fminf(fmaxf((16384.0f - Cv) / (Cv + 1e-6f), 1.0f), 50.0f);
        narrAcc += (double)pw * (double)Uv;
        valid   += (double)Cv;
    }
#pragma unroll
    for (int o = 16; o; o >>= 1) {
        subAcc  += __shfl_down_sync(0xffffffffu, subAcc,  o);
        narrAcc += __shfl_down_sync(0xffffffffu, narrAcc, o);
        valid   += __shfl_down_sync(0xffffffffu, valid,   o);
    }
    __shared__ double rd[24];
    if ((tid & 31) == 0) {
        int w = tid >> 5;   // 8 warps
        rd[w] = subAcc; rd[8 + w] = narrAcc; rd[16 + w] = valid;
    }
    __syncthreads();
    if (tid == 0) {
        double ss = 0.0, ns = 0.0, vv = 0.0;
        for (int i = 0; i < 8; i++) { ss += rd[i]; ns += rd[8 + i]; vv += rd[16 + i]; }
        double Qss = g_scl[0], Wns = g_scl[1];
        double hs = g_scl[2], nfs = g_scl[3], sfs = g_scl[4];

        // sub BCE total over gated elements: sum_c pw_c*A_c + sum g*(1-s)*spx
        double sub_total = ss + Qss;
        double narrative_loss = (ns + Wns) / (16384.0 * 128.0);
        double sub_loss = (vv > 0.0) ? (sub_total / 8.0) / fmax(vv, 1.0) : 0.0;
        double total = (narrative_loss - 0.1 * nfs / (16384.0 * 128.0))
                     + (sub_loss       - 0.1 * sfs / (16384.0 * 1024.0))
                     + 0.5 * hs / 16384.0;
        out[0] = (float)total;
    }
    __syncthreads();

    // reset scratch for the next graph replay
    for (int i = tid; i < NSHARD * NS; i += BLOCK_MAIN) {
        ((float*)g_sA)[i] = 0.f; ((float*)g_sC)[i] = 0.f;
    }
    for (int i = tid; i < NSHARD * NN; i += BLOCK_MAIN) {
        ((float*)g_nU)[i] = 0.f; ((float*)g_nC)[i] = 0.f;
    }
    if (tid < 8) g_scl[tid] = 0.f;
    if (tid == 0) g_ctr = 0u;
}

extern "C" void kernel_launch(void* const* d_in, const int* in_sizes, int n_in,
                              void* d_out, int out_size)
{
    const float* nlg = (const float*)d_in[0];   // narrative_logits [B,128]
    const float* slg = (const float*)d_in[1];   // subnarrative_logits [B,1024]
    const int*   nlb = (const int*)d_in[2];     // narrative_labels [B,128]
    const int*   slb = (const int*)d_in[3];     // subnarrative_labels [B,1024]
    (void)in_sizes; (void)n_in; (void)out_size;

    fused_kernel<<<GRID_MAIN, BLOCK_MAIN>>>(nlg, slg, nlb, slb, (float*)d_out);
}

// round 8
// speedup vs baseline: 1.8001x; 1.0398x over previous
#include <cuda_runtime.h>

#define B_ROWS 16384
#define NN     128
#define NS     1024
#define GRID_MAIN 296            // 2 blocks/SM * 148 SMs
#define BLOCK_MAIN 256
#define LANES (GRID_MAIN * 2)
#define NSHARD 4

// ---------------- scratch (device globals; statically zero-initialized) ----------------
// Invariant: zero at entry of every kernel_launch; finalizing block resets.
__device__ float g_sA[NSHARD][NS];   // sum g*s*softplus(-x)  (sub, pw-weighted part)
__device__ float g_sC[NSHARD][NS];   // sum s (ungated column count)
__device__ float g_nU[NSHARD][NN];   // sum y*softplus(-x)    (narrative)
__device__ float g_nC[NSHARD][NN];   // sum y
__device__ float g_scl[8];           // 0=Qs 1=Wn 2=hier 3=nf 4=sf
__device__ unsigned int g_ctr;

__device__ __forceinline__ float softplus_f(float x) {
    // softplus(x) = max(x,0) + log1p(exp(-|x|)); EX2 + LG2
    float e = exp2f(-1.4426950408889634f * fabsf(x));
    float L = __log2f(1.0f + e);
    return fmaxf(x, 0.0f) + 0.6931471805599453f * L;
}

__global__ __launch_bounds__(BLOCK_MAIN, 2)
void fused_kernel(const float* __restrict__ nlg, const float* __restrict__ slg,
                  const int* __restrict__ nlb,  const int* __restrict__ slb,
                  float* __restrict__ out)
{
    const int tid  = threadIdx.x;
    const int n    = tid & 127;                     // narrative class owned
    const int lane = blockIdx.x * 2 + (tid >> 7);   // row-processor id

    float A[8];
#pragma unroll
    for (int k = 0; k < 8; k++) A[k] = 0.f;
    float Un = 0.f, Qs = 0.f, Wn = 0.f, hier = 0.f, nf = 0.f, sf = 0.f;
    int cn = 0, ca = 0, cb = 0;   // packed byte-lane counts (<=28 per byte, safe)

    const float4* sp  = (const float4*)slg + (size_t)lane * (NS / 4) + n * 2;
    const int4*   slp = (const int4*)slb   + (size_t)lane * (NS / 4) + n * 2;
    const float*  np  = nlg + (size_t)lane * NN + n;
    const int*    nbp = nlb + (size_t)lane * NN + n;
    const size_t  sstep = (size_t)LANES * (NS / 4);
    const size_t  nstep = (size_t)LANES * NN;

    // ---- prologue: load row `lane` ----
    float4 v0 = __ldcs(sp), v1 = __ldcs(sp + 1);
    int4   l0 = __ldcs(slp), l1 = __ldcs(slp + 1);
    float  xn = __ldcs(np);
    int    gi = __ldcs(nbp);

    for (int r = lane; r < B_ROWS; r += LANES) {
        // ---- prefetch next row, UNCONDITIONAL (clamped: last iter reloads current row) ----
        const bool  more = (r + LANES) < B_ROWS;
        const size_t sadv = more ? sstep : 0;
        const size_t nadv = more ? nstep : 0;
        sp += sadv; slp += sadv; np += nadv; nbp += nadv;
        float4 nv0 = __ldcs(sp), nv1 = __ldcs(sp + 1);
        int4   nl0 = __ldcs(slp), nl1 = __ldcs(slp + 1);
        float  nxn = __ldcs(np);
        int    ngi = __ldcs(nbp);

        float g = (float)gi;

        // ---- narrative element: 3 MUFU (EX2, LG2, RCP) ----
        float e   = exp2f(-1.4426950408889634f * fabsf(xn));
        float t   = 1.0f + e;
        float q   = __fdividef(1.0f, t);                       // MUFU.RCP
        float spn = fmaxf(xn, 0.0f) + 0.6931471805599453f * __log2f(t);
        float spmn = spn - xn;                                 // softplus(-x)
        bool  posn = (xn >= 0.0f);
        float pn   = posn ? q : e * q;                         // sigmoid(xn)
        float ompn = posn ? e * q : q;                         // 1 - sigmoid(xn)
        nf = fmaf(g * ompn * ompn, -spmn, nf);
        Un = fmaf(g, spmn, Un);
        Wn = fmaf(1.0f - g, spn, Wn);
        cn += gi;

        // ---- 8 subnarrative elements of this group ----
        float xs[8] = { v0.x, v0.y, v0.z, v0.w, v1.x, v1.y, v1.z, v1.w };
        int   li[8] = { l0.x, l0.y, l0.z, l0.w, l1.x, l1.y, l1.z, l1.w };
        float mx = xs[0];
#pragma unroll
        for (int k = 0; k < 8; k++) {
            float x   = xs[k];
            float s   = __int_as_float(li[k] * 0x3f800000);  // 0/1 -> 0.0f/1.0f
            float spx = softplus_f(x);
            float spm = spx - x;
            float w   = exp2f(-2.8853900817779268f * spx);   // (1-p)^2
            sf  = fmaf(s * w, -spm, sf);                     // s*(1-p)^2*log sigmoid
            float gs = g * s;
            A[k] = fmaf(gs, spm, A[k]);
            Qs   = fmaf(g - gs, spx, Qs);                    // g*(1-s)*spx
            mx   = fmaxf(mx, x);
        }
        ca += li[0] + (li[1] << 8) + (li[2] << 16) + (li[3] << 24);
        cb += li[4] + (li[5] << 8) + (li[6] << 16) + (li[7] << 24);

        // ---- hierarchy: max(sigmoid)=sigmoid(max) ----
        float em = exp2f(-1.4426950408889634f * mx);
        float pm = __fdividef(1.0f, 1.0f + em);
        hier = fmaf(g, fmaxf(pm - pn, 0.0f), hier);

        // rotate double-buffer
        v0 = nv0; v1 = nv1; l0 = nl0; l1 = nl1; xn = nxn; gi = ngi;
    }

    // ---------------- pair the two 128-lane halves in shared ----------------
    __shared__ float sh[128][17];    // odd stride -> conflict-free
    if (tid >= 128) {
        float* d = sh[tid - 128];
#pragma unroll
        for (int k = 0; k < 8; k++) d[k] = A[k];
        d[8] = Un; d[9] = Qs; d[10] = Wn; d[11] = hier; d[12] = nf; d[13] = sf;
        d[14] = __int_as_float(cn); d[15] = __int_as_float(ca); d[16] = __int_as_float(cb);
    }
    __syncthreads();

    const int shard = blockIdx.x & (NSHARD - 1);
    if (tid < 128) {
        float* d = sh[tid];
#pragma unroll
        for (int k = 0; k < 8; k++) A[k] += d[k];
        Un += d[8]; Qs += d[9]; Wn += d[10]; hier += d[11]; nf += d[12]; sf += d[13];
        cn += __float_as_int(d[14]);
        ca += __float_as_int(d[15]);
        cb += __float_as_int(d[16]);

        atomicAdd(&g_nU[shard][n], Un);
        atomicAdd(&g_nC[shard][n], (float)cn);
#pragma unroll
        for (int k = 0; k < 8; k++)
            atomicAdd(&g_sA[shard][n * 8 + k], A[k]);
#pragma unroll
        for (int k = 0; k < 4; k++) {
            atomicAdd(&g_sC[shard][n * 8 + k],     (float)((ca >> (8 * k)) & 255));
            atomicAdd(&g_sC[shard][n * 8 + 4 + k], (float)((cb >> (8 * k)) & 255));
        }
    }

    // scalar block-reduce over lower 128 threads (4 full warps)
    __shared__ float sw[5][4];
    if (tid < 128) {
#pragma unroll
        for (int o = 16; o; o >>= 1) {
            Qs   += __shfl_down_sync(0xffffffffu, Qs,   o);
            Wn   += __shfl_down_sync(0xffffffffu, Wn,   o);
            hier += __shfl_down_sync(0xffffffffu, hier, o);
            nf   += __shfl_down_sync(0xffffffffu, nf,   o);
            sf   += __shfl_down_sync(0xffffffffu, sf,   o);
        }
        if ((tid & 31) == 0) {
            int w = tid >> 5;
            sw[0][w] = Qs; sw[1][w] = Wn; sw[2][w] = hier; sw[3][w] = nf; sw[4][w] = sf;
        }
    }
    __syncthreads();
    if (tid < 5) {
        float v = sw[tid][0] + sw[tid][1] + sw[tid][2] + sw[tid][3];
        atomicAdd(&g_scl[tid], v);
    }

    // ---------------- last block finalizes and resets scratch ----------------
    __threadfence();
    __shared__ unsigned int s_last;
    if (tid == 0) s_last = (atomicAdd(&g_ctr, 1u) == (unsigned)(gridDim.x - 1)) ? 1u : 0u;
    __syncthreads();
    if (!s_last) return;
    __threadfence();

    double subAcc = 0.0, narrAcc = 0.0, valid = 0.0;
    for (int c = tid; c < NS; c += BLOCK_MAIN) {
        float Av = g_sA[0][c] + g_sA[1][c] + g_sA[2][c] + g_sA[3][c];
        float Cv = g_sC[0][c] + g_sC[1][c] + g_sC[2][c] + g_sC[3][c];
        float pw = fminf(fmaxf((16384.0f - Cv) / (Cv + 1e-6f), 1.0f), 50.0f);
        subAcc += (double)pw * (double)Av;
    }
    for (int c = tid; c < NN; c += BLOCK_MAIN) {
        float Uv = g_nU[0][c] + g_nU[1][c] + g_nU[2][c] + g_nU[3][c];
        float Cv = g_nC[0][c] + g_nC[1][c] + g_nC[2][c] + g_nC[3][c];
        float pw = fminf(fmaxf((16384.0f - Cv) / (Cv + 1e-6f), 1.0f), 50.0f);
        narrAcc += (double)pw * (double)Uv;
        valid   += (double)Cv;
    }
#pragma unroll
    for (int o = 16; o; o >>= 1) {
        subAcc  += __shfl_down_sync(0xffffffffu, subAcc,  o);
        narrAcc += __shfl_down_sync(0xffffffffu, narrAcc, o);
        valid   += __shfl_down_sync(0xffffffffu, valid,   o);
    }
    __shared__ double rd[24];
    if ((tid & 31) == 0) {
        int w = tid >> 5;   // 8 warps
        rd[w] = subAcc; rd[8 + w] = narrAcc; rd[16 + w] = valid;
    }
    __syncthreads();
    if (tid == 0) {
        double ss = 0.0, ns = 0.0, vv = 0.0;
        for (int i = 0; i < 8; i++) { ss += rd[i]; ns += rd[8 + i]; vv += rd[16 + i]; }
        double Qss = g_scl[0], Wns = g_scl[1];
        double hs = g_scl[2], nfs = g_scl[3], sfs = g_scl[4];

        double sub_total = ss + Qss;
        double narrative_loss = (ns + Wns) / (16384.0 * 128.0);
        double sub_loss = (vv > 0.0) ? (sub_total / 8.0) / fmax(vv, 1.0) : 0.0;
        double total = (narrative_loss - 0.1 * nfs / (16384.0 * 128.0))
                     + (sub_loss       - 0.1 * sfs / (16384.0 * 1024.0))
                     + 0.5 * hs / 16384.0;
        out[0] = (float)total;
    }
    __syncthreads();

    // reset scratch for the next graph replay
    for (int i = tid; i < NSHARD * NS; i += BLOCK_MAIN) {
        ((float*)g_sA)[i] = 0.f; ((float*)g_sC)[i] = 0.f;
    }
    for (int i = tid; i < NSHARD * NN; i += BLOCK_MAIN) {
        ((float*)g_nU)[i] = 0.f; ((float*)g_nC)[i] = 0.f;
    }
    if (tid < 8) g_scl[tid] = 0.f;
    if (tid == 0) g_ctr = 0u;
}

extern "C" void kernel_launch(void* const* d_in, const int* in_sizes, int n_in,
                              void* d_out, int out_size)
{
    const float* nlg = (const float*)d_in[0];   // narrative_logits [B,128]
    const float* slg = (const float*)d_in[1];   // subnarrative_logits [B,1024]
    const int*   nlb = (const int*)d_in[2];     // narrative_labels [B,128]
    const int*   slb = (const int*)d_in[3];     // subnarrative_labels [B,1024]
    (void)in_sizes; (void)n_in; (void)out_size;

    fused_kernel<<<GRID_MAIN, BLOCK_MAIN>>>(nlg, slg, nlb, slb, (float*)d_out);
}